// round 10
// baseline (speedup 1.0000x reference)
#include <cuda_runtime.h>
#include <math.h>
#include <stdint.h>

#define NROWS 32768      // 32 * 32 * 32 vectors
#define DDIM  256
#define KCODES 1024
#define HW    1024
#define CHW   (DDIM*HW)
#define OUT_ELEMS 8388608
#define GBLK  2048

// ---- scratch (device globals; no allocation allowed) ----
__device__ float g_cnorm[KCODES];
__device__ float g_xnorm[NROWS];
__device__ int   g_idx[NROWS];
__device__ int   g_counts[KCODES];
__device__ float g_loss_part[GBLK];
__device__ float g_thr[NROWS];                     // rescue threshold; -3.4e38 => unflagged
__device__ unsigned g_cmax;                        // bits of max |codebook| (same value every replay)
__device__ float g_dist[(size_t)NROWS * KCODES];   // 128MB screening distance matrix

// ---- smem layout for vq_mma (floats) ----
// A_s [k=256][stride 136] : 34816   (bank-safe: 136 mod 32 == 8)
// B_s [k=32][stride 136]  :  4352   (reused as merge buffer after GEMM)
// xn_s[128], sx_s[128]
#define SA      136
#define OFF_B   34816
#define OFF_XN  39168
#define OFF_SX  39296
#define OFF_MRG OFF_B
#define SMEM_DYN ((39296 + 128) * 4)

__device__ __forceinline__ uint32_t f2tf(float f) {
    uint32_t u; asm("cvt.rna.tf32.f32 %0, %1;" : "=r"(u) : "f"(f)); return u;
}
#define MMA8(d, a0_, a1_, a2_, a3_, b0_, b1_)                              \
    asm volatile("mma.sync.aligned.m16n8k8.row.col.f32.tf32.tf32.f32 "     \
        "{%0,%1,%2,%3}, {%4,%5,%6,%7}, {%8,%9}, {%0,%1,%2,%3};"            \
        : "+f"((d)[0]), "+f"((d)[1]), "+f"((d)[2]), "+f"((d)[3])           \
        : "r"(a0_), "r"(a1_), "r"(a2_), "r"(a3_), "r"(b0_), "r"(b1_))

// ============================================================
// Kernel A: codebook norms + max|c| + zero histogram
// ============================================================
__global__ void prep_cnorm(const float* __restrict__ cb) {
    int w    = (blockIdx.x * blockDim.x + threadIdx.x) >> 5;
    int lane = threadIdx.x & 31;
    if (w >= KCODES) return;
    const float* row = cb + (size_t)w * DDIM;
    float s = 0.f, mx = 0.f;
    #pragma unroll
    for (int d = lane; d < DDIM; d += 32) {
        float v = row[d];
        s  = __fadd_rn(s, __fmul_rn(v, v));
        mx = fmaxf(mx, fabsf(v));
    }
    #pragma unroll
    for (int o = 16; o; o >>= 1) {
        s += __shfl_down_sync(0xffffffffu, s, o);
        mx = fmaxf(mx, __shfl_down_sync(0xffffffffu, mx, o));
    }
    if (lane == 0) {
        g_cnorm[w] = s; g_counts[w] = 0;
        atomicMax(&g_cmax, __float_as_uint(mx));  // positive floats: uint order == float order
    }
}

// ============================================================
// Kernel B: TF32 mma.sync screening GEMM (x @ cb^T) -> dist, min1/min2, flag.
// CTA: 128 rows x 1024 codes (8 N-passes x 8 K-chunks), A resident in smem.
// ============================================================
__global__ __launch_bounds__(256, 1)
void vq_mma(const float* __restrict__ x, const float* __restrict__ cb) {
    extern __shared__ float sm[];
    float*  A_s  = sm;
    float*  B_s  = sm + OFF_B;
    float*  xn_s = sm + OFF_XN;
    float*  sx_s = sm + OFF_SX;
    float4* mrg  = (float4*)(sm + OFF_MRG);

    const int tid = threadIdx.x;
    const int m0  = blockIdx.x * 128;
    const int bb  = m0 >> 10, hw0 = m0 & 1023;

    // ---- load A (x slice) into A_s[k][row]: coalesced LDG, conflict-free STS
    {
        const int r = tid & 127, half = tid >> 7;
        const float* xp = x + (size_t)bb * CHW + (size_t)(half * 128) * HW + hw0 + r;
        #pragma unroll 4
        for (int d = 0; d < 128; d++)
            A_s[(half * 128 + d) * SA + r] = xp[(size_t)d * HW];
    }
    __syncthreads();
    // xnorm: strictly sequential d=0..255 (reference rounding) + sum|x| for margin
    if (tid < 128) {
        float s = 0.f, ax = 0.f;
        #pragma unroll 8
        for (int d = 0; d < 256; d++) {
            float v = A_s[d * SA + tid];
            s  = __fadd_rn(s, __fmul_rn(v, v));
            ax += fabsf(v);
        }
        xn_s[tid] = s; sx_s[tid] = ax; g_xnorm[m0 + tid] = s;
    }

    const int lane = tid & 31, warp = tid >> 5;
    const int wm = warp >> 2, wn = warp & 3;        // 2x4 warp grid; warp tile 64x32
    const int g  = lane >> 2, t  = lane & 3;

    // B chunk load mapping: 128 codes x 32 k per chunk; 64B contiguous per thread
    const int bcode = (tid & 31) + 32 * ((tid >> 5) & 3);
    const int bkq   = (tid >> 7) * 16;

    float acc[4][4][4];
    #pragma unroll
    for (int i = 0; i < 4; i++)
        #pragma unroll
        for (int j = 0; j < 4; j++)
            #pragma unroll
            for (int q = 0; q < 4; q++) acc[i][j][q] = 0.f;

    float sv1[8], sv2[8]; int si1[8];               // 8 row-slots per lane
    #pragma unroll
    for (int s8 = 0; s8 < 8; s8++) { sv1[s8] = 3.4e38f; sv2[s8] = 3.4e38f; si1[s8] = 0; }

    float pre[16];
    {   // prefetch chunk 0
        const float4* p = (const float4*)(cb + (size_t)bcode * DDIM + bkq);
        #pragma unroll
        for (int i = 0; i < 4; i++) {
            float4 q = p[i];
            pre[4*i] = q.x; pre[4*i+1] = q.y; pre[4*i+2] = q.z; pre[4*i+3] = q.w;
        }
    }
    __syncthreads();
    #pragma unroll
    for (int i = 0; i < 4; i++)
        #pragma unroll
        for (int e = 0; e < 4; e++)
            B_s[(bkq + i * 4 + e) * SA + bcode] = pre[4*i + e];
    __syncthreads();

    #pragma unroll 1
    for (int chunk = 0; chunk < 64; chunk++) {
        const int kc = chunk & 7, nt = chunk >> 3;
        if (chunk < 63) {                            // prefetch next chunk into regs
            const int c2 = chunk + 1;
            const float4* p = (const float4*)(cb + (size_t)(((c2 >> 3) * 128) + bcode) * DDIM
                                              + (c2 & 7) * 32 + bkq);
            #pragma unroll
            for (int i = 0; i < 4; i++) {
                float4 q = p[i];
                pre[4*i] = q.x; pre[4*i+1] = q.y; pre[4*i+2] = q.z; pre[4*i+3] = q.w;
            }
        }
        // ---- MMAs over this 32-k chunk
        #pragma unroll
        for (int ks = 0; ks < 4; ks++) {
            const int ka = kc * 32 + ks * 8;
            uint32_t af[4][4];
            #pragma unroll
            for (int im = 0; im < 4; im++) {
                const int rb = wm * 64 + im * 16 + g;
                af[im][0] = f2tf(A_s[(ka + t) * SA + rb]);
                af[im][1] = f2tf(A_s[(ka + t) * SA + rb + 8]);
                af[im][2] = f2tf(A_s[(ka + t + 4) * SA + rb]);
                af[im][3] = f2tf(A_s[(ka + t + 4) * SA + rb + 8]);
            }
            #pragma unroll
            for (int jn = 0; jn < 4; jn++) {
                const int nb = wn * 32 + jn * 8 + g;
                uint32_t b0 = f2tf(B_s[(ks * 8 + t) * SA + nb]);
                uint32_t b1 = f2tf(B_s[(ks * 8 + t + 4) * SA + nb]);
                #pragma unroll
                for (int im = 0; im < 4; im++)
                    MMA8(acc[im][jn], af[im][0], af[im][1], af[im][2], af[im][3], b0, b1);
            }
        }
        // ---- per-N-pass epilogue: dist, store, min1/min2
        if (kc == 7) {
            #pragma unroll
            for (int im = 0; im < 4; im++) {
                const int rl = wm * 64 + im * 16 + g;
                const float xnA = xn_s[rl], xnB = xn_s[rl + 8];
                const int s0 = im * 2, s1 = im * 2 + 1;
                #pragma unroll
                for (int jn = 0; jn < 4; jn++) {
                    const int col = nt * 128 + wn * 32 + jn * 8 + 2 * t;
                    const float2 cn = *(const float2*)&g_cnorm[col];
                    float d00 = __fadd_rn(__fadd_rn(xnA, cn.x), -2.f * acc[im][jn][0]);
                    float d01 = __fadd_rn(__fadd_rn(xnA, cn.y), -2.f * acc[im][jn][1]);
                    float d10 = __fadd_rn(__fadd_rn(xnB, cn.x), -2.f * acc[im][jn][2]);
                    float d11 = __fadd_rn(__fadd_rn(xnB, cn.y), -2.f * acc[im][jn][3]);
                    *(float2*)&g_dist[(size_t)(m0 + rl) * KCODES + col]     = make_float2(d00, d01);
                    *(float2*)&g_dist[(size_t)(m0 + rl + 8) * KCODES + col] = make_float2(d10, d11);
                    if (d00 < sv1[s0] || (d00 == sv1[s0] && col     < si1[s0])) { sv2[s0]=sv1[s0]; sv1[s0]=d00; si1[s0]=col;   }
                    else if (d00 < sv2[s0]) sv2[s0] = d00;
                    if (d01 < sv1[s0] || (d01 == sv1[s0] && col + 1 < si1[s0])) { sv2[s0]=sv1[s0]; sv1[s0]=d01; si1[s0]=col+1; }
                    else if (d01 < sv2[s0]) sv2[s0] = d01;
                    if (d10 < sv1[s1] || (d10 == sv1[s1] && col     < si1[s1])) { sv2[s1]=sv1[s1]; sv1[s1]=d10; si1[s1]=col;   }
                    else if (d10 < sv2[s1]) sv2[s1] = d10;
                    if (d11 < sv1[s1] || (d11 == sv1[s1] && col + 1 < si1[s1])) { sv2[s1]=sv1[s1]; sv1[s1]=d11; si1[s1]=col+1; }
                    else if (d11 < sv2[s1]) sv2[s1] = d11;
                    acc[im][jn][0] = acc[im][jn][1] = acc[im][jn][2] = acc[im][jn][3] = 0.f;
                }
            }
        }
        __syncthreads();
        if (chunk < 63) {
            #pragma unroll
            for (int i = 0; i < 4; i++)
                #pragma unroll
                for (int e = 0; e < 4; e++)
                    B_s[(bkq + i * 4 + e) * SA + bcode] = pre[4*i + e];
            __syncthreads();
        }
    }

    // ---- merge across t-lanes (lanes with same g share rows)
    #pragma unroll
    for (int s8 = 0; s8 < 8; s8++) {
        #pragma unroll
        for (int o = 1; o <= 2; o <<= 1) {
            float ov1 = __shfl_xor_sync(0xffffffffu, sv1[s8], o);
            int   oi1 = __shfl_xor_sync(0xffffffffu, si1[s8], o);
            float ov2 = __shfl_xor_sync(0xffffffffu, sv2[s8], o);
            if (ov1 < sv1[s8] || (ov1 == sv1[s8] && oi1 < si1[s8])) {
                sv2[s8] = fminf(sv1[s8], ov2); sv1[s8] = ov1; si1[s8] = oi1;
            } else {
                sv2[s8] = fminf(ov1, sv2[s8]);
            }
        }
    }
    if (t == 0) {
        #pragma unroll
        for (int s8 = 0; s8 < 8; s8++) {
            const int row = wm * 64 + (s8 >> 1) * 16 + (s8 & 1) * 8 + g;
            mrg[row * 4 + wn] = make_float4(sv1[s8], __int_as_float(si1[s8]), sv2[s8], 0.f);
        }
    }
    __syncthreads();
    // ---- merge across wn warps + flag
    if (tid < 128) {
        float4 e = mrg[tid * 4];
        float V1 = e.x; int I1 = __float_as_int(e.y); float V2 = e.z;
        #pragma unroll
        for (int k = 1; k < 4; k++) {
            float4 f = mrg[tid * 4 + k];
            float ov1 = f.x; int oi1 = __float_as_int(f.y); float ov2 = f.z;
            if (ov1 < V1 || (ov1 == V1 && oi1 < I1)) { V2 = fminf(V1, ov2); V1 = ov1; I1 = oi1; }
            else V2 = fminf(ov1, V2);
        }
        // tf32 dist error bound: 2 * 2^-10 * sum|x| * max|c|; margin = 1.5x + slack
        float marg = 0.003f * sx_s[tid] * __uint_as_float(g_cmax) + 5e-5f;
        g_idx[m0 + tid] = I1;
        g_thr[m0 + tid] = (V2 - V1 < marg) ? (V1 + marg) : -3.4e38f;
    }
}

// ============================================================
// Kernel C: rescue — exact fp32 rescore of candidates for flagged rows
// (arithmetic identical to the R1 kernel that matched the reference).
// ============================================================
__global__ void rescue_kernel(const float* __restrict__ x, const float* __restrict__ cb) {
    const int w     = (blockIdx.x * blockDim.x + threadIdx.x) >> 5;
    const int lane  = threadIdx.x & 31;
    const int nwarp = (gridDim.x * blockDim.x) >> 5;
    for (int row = w; row < NROWS; row += nwarp) {
        float thr = g_thr[row];
        if (thr < -1e37f) continue;
        const int bb = row >> 10, hw = row & 1023;
        const float* xp = x + (size_t)bb * CHW + hw;
        const float xn = g_xnorm[row];
        const float* dr = g_dist + (size_t)row * KCODES;
        float bv = 3.4e38f; int bi = 0x7fffffff;
        for (int c = lane; c < KCODES; c += 32) {
            if (dr[c] <= thr) {
                float dot = 0.f;
                #pragma unroll 8
                for (int d = 0; d < DDIM; d++)
                    dot = fmaf(xp[(size_t)d * HW], cb[(size_t)c * DDIM + d], dot);
                float dist = __fadd_rn(__fadd_rn(xn, g_cnorm[c]), -2.f * dot);
                if (dist < bv || (dist == bv && c < bi)) { bv = dist; bi = c; }
            }
        }
        #pragma unroll
        for (int o = 16; o; o >>= 1) {
            float ov = __shfl_down_sync(0xffffffffu, bv, o);
            int   oi = __shfl_down_sync(0xffffffffu, bi, o);
            if (ov < bv || (ov == bv && oi < bi)) { bv = ov; bi = oi; }
        }
        if (lane == 0) g_idx[row] = bi;
    }
}

// ============================================================
// Kernel D: histogram from final indices
// ============================================================
__global__ void hist_kernel() {
    int i = blockIdx.x * 256 + threadIdx.x;
    atomicAdd(&g_counts[g_idx[i]], 1);
}

// ============================================================
// Kernel E: gather + straight-through output + loss partials
// ============================================================
__global__ void gather_kernel(const float* __restrict__ x,
                              const float* __restrict__ cb,
                              float* __restrict__ out) {
    __shared__ float wsum[8];
    const int bid = blockIdx.x;                 // 2048
    const int b   = bid >> 6;
    const int r   = bid & 63;
    const int hw0 = (r & 15) << 6;
    const int d0  = (r >> 4) << 6;
    const int t   = threadIdx.x;
    const int hw  = hw0 + (t & 63);
    const int db  = d0 + (t >> 6) * 16;
    const int n   = (b << 10) | hw;
    const int k   = g_idx[n];

    const float4* crow = (const float4*)(cb + (size_t)k * DDIM + db);
    const size_t xb = (size_t)b * CHW + (size_t)db * HW + hw;
    float s = 0.f;
    #pragma unroll
    for (int g = 0; g < 4; g++) {
        float4 q = crow[g];
        float qv[4] = {q.x, q.y, q.z, q.w};
        #pragma unroll
        for (int i = 0; i < 4; i++) {
            size_t idx = xb + (size_t)(g * 4 + i) * HW;
            float xv = x[idx];
            float rr = __fsub_rn(qv[i], xv);     // stop_gradient(q - x)
            out[idx] = __fadd_rn(xv, rr);        // straight-through
            s = fmaf(rr, rr, s);
        }
    }
    #pragma unroll
    for (int o = 16; o; o >>= 1) s += __shfl_down_sync(0xffffffffu, s, o);
    if ((t & 31) == 0) wsum[t >> 5] = s;
    __syncthreads();
    if (t < 8) {
        float v = wsum[t];
        #pragma unroll
        for (int o = 4; o; o >>= 1) v += __shfl_down_sync(0xffu, v, o);
        if (t == 0) g_loss_part[bid] = v;
    }
}

// ============================================================
// Kernel F: finalize loss + perplexity into output tail
// ============================================================
__global__ void finalize_kernel(float* __restrict__ out, int loss_off) {
    __shared__ double sh[256];
    int tid = threadIdx.x;

    double ls = 0.0;
    for (int i = tid; i < GBLK; i += 256) ls += (double)g_loss_part[i];
    double es = 0.0;
    for (int k = tid; k < KCODES; k += 256) {
        double p = (double)g_counts[k] * (1.0 / 32768.0);
        es += p * log(p + 1e-10);
    }

    sh[tid] = ls; __syncthreads();
    for (int s2 = 128; s2; s2 >>= 1) { if (tid < s2) sh[tid] += sh[tid + s2]; __syncthreads(); }
    double total_loss = sh[0];
    __syncthreads();

    sh[tid] = es; __syncthreads();
    for (int s2 = 128; s2; s2 >>= 1) { if (tid < s2) sh[tid] += sh[tid + s2]; __syncthreads(); }

    if (tid == 0) {
        double mean = total_loss / (double)OUT_ELEMS;
        out[loss_off]     = (float)(mean + 0.25 * mean);
        out[loss_off + 1] = (float)exp(-sh[0]);
    }
}

// ============================================================
extern "C" void kernel_launch(void* const* d_in, const int* in_sizes, int n_in,
                              void* d_out, int out_size) {
    const float* x  = (const float*)d_in[0];   // [32,256,32,32]
    const float* cb = (const float*)d_in[1];   // [1024,256]
    float* out = (float*)d_out;

    cudaFuncSetAttribute(vq_mma,
                         cudaFuncAttributeMaxDynamicSharedMemorySize, SMEM_DYN);

    prep_cnorm<<<(KCODES * 32 + 255) / 256, 256>>>(cb);
    vq_mma<<<NROWS / 128, 256, SMEM_DYN>>>(x, cb);
    rescue_kernel<<<256, 256>>>(x, cb);
    hist_kernel<<<NROWS / 256, 256>>>();
    gather_kernel<<<GBLK, 256>>>(x, cb, out);
    finalize_kernel<<<1, 256>>>(out, out_size - 2);
}